// round 1
// baseline (speedup 1.0000x reference)
#include <cuda_runtime.h>

// SORF: out[m] = sum_a FEAT_NORM * sum_f cos( (1/16)*H*(D_{s,j} ⊙ proj_a) + bias_s ) * alpha
// with proj_a = rep[m,a,:] @ reductors[s], s = charges[m,a]. Only the owned charge
// channel contributes, so we group atoms by charge and compute one channel per atom.

#define ATOMS 8
#define NATOMS 2048          // M*A = 32*64
#define NBLK (NATOMS / ATOMS) // 256

__device__ int g_count[4];
__device__ int g_list[4 * NATOMS];

__global__ void prep_kernel(const int* __restrict__ charges, float* __restrict__ out) {
    int tid = threadIdx.x;
    if (tid < 4) g_count[tid] = 0;
    if (tid < 32) out[tid] = 0.0f;
    __syncthreads();
    for (int i = tid; i < NATOMS; i += 256) {
        int s = charges[i];
        int idx = atomicAdd(&g_count[s], 1);
        g_list[s * NATOMS + idx] = i;
    }
}

#define BFLY(a, b) do { float t_ = (a); (a) = t_ + (b); (b) = t_ - (b); } while (0)

__global__ void __launch_bounds__(256) sorf_kernel(
    const float* __restrict__ rep,
    const float* __restrict__ reductors,
    const float* __restrict__ Dmat,
    const float* __restrict__ bias,
    const float* __restrict__ alpha,
    float* __restrict__ out)
{
    const int s = blockIdx.y;
    const int n = g_count[s];
    const int start = blockIdx.x * ATOMS;
    if (start >= n) return;
    const int cnt = min(ATOMS, n - start);

    // Static smem: 8192 (rep phase1 / bias phase2, overlaid) + 2048 proj + bits + atoms ≈ 42 KB
    __shared__ float repbiasS[8192];
    __shared__ float projS[ATOMS * 256];
    __shared__ unsigned dbitsS[256];   // 32 stacks x 8 words of sign bits
    __shared__ int atomsS[ATOMS];

    const int tid = threadIdx.x;
    const int lane = tid & 31;
    const int w = tid >> 5;

    if (tid < ATOMS) atomsS[tid] = (tid < cnt) ? g_list[s * NATOMS + start + tid] : -1;
    __syncthreads();

    // rep tile -> smem (zero-fill missing atoms), vectorized
    {
        float4* dst = (float4*)repbiasS;
        const float4* src = (const float4*)rep;
        #pragma unroll
        for (int it = 0; it < (ATOMS * 128) / 256; ++it) {
            int idx = tid + 256 * it;
            int ai = idx >> 7, v = idx & 127;
            int atom = atomsS[ai];
            dst[idx] = (atom >= 0) ? src[atom * 128 + v] : make_float4(0.f, 0.f, 0.f, 0.f);
        }
    }
    // D sign bits via ballot: bit p%32 of word p/32 set iff Dmat < 0 (==> multiply by -1)
    {
        const float* dsrc = Dmat + s * 8192;
        for (int k = 0; k < 32; ++k) {
            int word = w * 32 + k;
            float dv = dsrc[word * 32 + lane];
            unsigned b = __ballot_sync(0xffffffffu, dv < 0.0f);
            if (lane == 0) dbitsS[word] = b;
        }
    }
    __syncthreads();

    // ---------------- Phase 1: proj[i][tid] = (1/16) * sum_r rep[i][r] * red[s][r][tid]
    float acc[ATOMS];
    #pragma unroll
    for (int i = 0; i < ATOMS; ++i) acc[i] = 0.f;
    {
        const float* redp = reductors + (size_t)s * 512 * 256 + tid;
        const float4* repS4 = (const float4*)repbiasS;
        #pragma unroll 1
        for (int r0 = 0; r0 < 512; r0 += 4) {
            float rd0 = redp[(r0 + 0) * 256];
            float rd1 = redp[(r0 + 1) * 256];
            float rd2 = redp[(r0 + 2) * 256];
            float rd3 = redp[(r0 + 3) * 256];
            int rq = r0 >> 2;
            #pragma unroll
            for (int i = 0; i < ATOMS; ++i) {
                float4 a4 = repS4[i * 128 + rq];   // broadcast LDS.128
                acc[i] = fmaf(a4.x, rd0, acc[i]);
                acc[i] = fmaf(a4.y, rd1, acc[i]);
                acc[i] = fmaf(a4.z, rd2, acc[i]);
                acc[i] = fmaf(a4.w, rd3, acc[i]);
            }
        }
    }
    __syncthreads();   // all done reading rep before bias overlays it
    #pragma unroll
    for (int i = 0; i < ATOMS; ++i) projS[i * 256 + tid] = acc[i] * 0.0625f;
    {
        float4* dst = (float4*)repbiasS;
        const float4* src = (const float4*)(bias + s * 8192);
        #pragma unroll
        for (int it = 0; it < 8; ++it) dst[tid + 256 * it] = src[tid + 256 * it];
    }
    __syncthreads();

    // ---------------- Phase 2: warp w handles atom w; 32 stacks of FWHT(256) + cos-dot
    // Element map: x[c]   holds p = 4*lane + c        (c = 0..3)
    //              x[4+c] holds p = 128 + 4*lane + c
    // Register stages: h=1,2,128.  Shfl stages: h=4,8,16,32,64 -> bfly masks 1,2,4,8,16.
    if (w < cnt) {
        const float4* pj4 = (const float4*)(projS + w * 256);
        const float4* bb4 = (const float4*)repbiasS;
        const float4* al4 = (const float4*)alpha;
        const int wsh = 4 * (lane & 7);
        const int widx = lane >> 3;
        float partial = 0.f;

        for (int j = 0; j < 32; ++j) {
            float4 xa = pj4[lane];
            float4 xb = pj4[lane + 32];
            float x0 = xa.x, x1 = xa.y, x2 = xa.z, x3 = xa.w;
            float x4 = xb.x, x5 = xb.y, x6 = xb.z, x7 = xb.w;

            unsigned n0 = dbitsS[j * 8 + widx] >> wsh;       // sign nibble for x0..x3
            unsigned n1 = dbitsS[j * 8 + 4 + widx] >> wsh;   // sign nibble for x4..x7
            x0 = __uint_as_float(__float_as_uint(x0) ^ ((n0 << 31) & 0x80000000u));
            x1 = __uint_as_float(__float_as_uint(x1) ^ ((n0 << 30) & 0x80000000u));
            x2 = __uint_as_float(__float_as_uint(x2) ^ ((n0 << 29) & 0x80000000u));
            x3 = __uint_as_float(__float_as_uint(x3) ^ ((n0 << 28) & 0x80000000u));
            x4 = __uint_as_float(__float_as_uint(x4) ^ ((n1 << 31) & 0x80000000u));
            x5 = __uint_as_float(__float_as_uint(x5) ^ ((n1 << 30) & 0x80000000u));
            x6 = __uint_as_float(__float_as_uint(x6) ^ ((n1 << 29) & 0x80000000u));
            x7 = __uint_as_float(__float_as_uint(x7) ^ ((n1 << 28) & 0x80000000u));

            // register butterflies: h=1, h=2, h=128
            BFLY(x0, x1); BFLY(x2, x3); BFLY(x4, x5); BFLY(x6, x7);
            BFLY(x0, x2); BFLY(x1, x3); BFLY(x4, x6); BFLY(x5, x7);
            BFLY(x0, x4); BFLY(x1, x5); BFLY(x2, x6); BFLY(x3, x7);

            // cross-lane butterflies: h = 4,8,16,32,64
            #pragma unroll
            for (int m = 1; m <= 16; m <<= 1) {
                float sgn = (lane & m) ? -1.f : 1.f;
                x0 = fmaf(x0, sgn, __shfl_xor_sync(0xffffffffu, x0, m));
                x1 = fmaf(x1, sgn, __shfl_xor_sync(0xffffffffu, x1, m));
                x2 = fmaf(x2, sgn, __shfl_xor_sync(0xffffffffu, x2, m));
                x3 = fmaf(x3, sgn, __shfl_xor_sync(0xffffffffu, x3, m));
                x4 = fmaf(x4, sgn, __shfl_xor_sync(0xffffffffu, x4, m));
                x5 = fmaf(x5, sgn, __shfl_xor_sync(0xffffffffu, x5, m));
                x6 = fmaf(x6, sgn, __shfl_xor_sync(0xffffffffu, x6, m));
                x7 = fmaf(x7, sgn, __shfl_xor_sync(0xffffffffu, x7, m));
            }

            float4 b0 = bb4[j * 64 + lane];
            float4 b1 = bb4[j * 64 + 32 + lane];
            float4 a0 = __ldg(&al4[j * 64 + lane]);
            float4 a1 = __ldg(&al4[j * 64 + 32 + lane]);
            partial = fmaf(__cosf(x0 + b0.x), a0.x, partial);
            partial = fmaf(__cosf(x1 + b0.y), a0.y, partial);
            partial = fmaf(__cosf(x2 + b0.z), a0.z, partial);
            partial = fmaf(__cosf(x3 + b0.w), a0.w, partial);
            partial = fmaf(__cosf(x4 + b1.x), a1.x, partial);
            partial = fmaf(__cosf(x5 + b1.y), a1.y, partial);
            partial = fmaf(__cosf(x6 + b1.z), a1.z, partial);
            partial = fmaf(__cosf(x7 + b1.w), a1.w, partial);
        }

        #pragma unroll
        for (int o = 16; o; o >>= 1) partial += __shfl_xor_sync(0xffffffffu, partial, o);
        if (lane == 0) {
            int atom = atomsS[w];
            atomicAdd(&out[atom >> 6], partial * 0.015625f);  // FEAT_NORM = 1/64
        }
    }
}

extern "C" void kernel_launch(void* const* d_in, const int* in_sizes, int n_in,
                              void* d_out, int out_size) {
    (void)in_sizes; (void)n_in; (void)out_size;
    const float* rep       = (const float*)d_in[0];
    const int*   charges   = (const int*)d_in[1];
    const float* reductors = (const float*)d_in[2];
    const float* Dmat      = (const float*)d_in[3];
    const float* bias      = (const float*)d_in[4];
    const float* alpha     = (const float*)d_in[5];
    float* out = (float*)d_out;

    prep_kernel<<<1, 256>>>(charges, out);
    sorf_kernel<<<dim3(NBLK, 4), 256>>>(rep, reductors, Dmat, bias, alpha, out);
}